// round 17
// baseline (speedup 1.0000x reference)
#include <cuda_runtime.h>
#include <cstdint>

// WeightedFeatureInteraction: out[b] = sum_{i<j} w[i,j] * <x[b,i,:], x[b,j,:]>
//   inputs [B, 64*128] fp32, field_weights [64,64] fp32, out [B,1] fp32.
//
// Round 16: R14 (CTA-per-batch-row, sequential 32KB streaming, cooperative
// tf32 mma Gram) with the K-coverage bug fixed: warp wq now computes ksteps
// {wq, wq+4, wq+8, wq+12} (16 k8-steps total across 4 warps = full K=128;
// R14 only covered k<64).

#define NF 64
#define ND 128
#define THREADS 128
#define NTILES 20
#define WBYTES (NTILES * 128 * 4)      // 10240: masked W fragments
#define ROW_WORDS (NF * ND)            // 8192 words = 32KB per batch row
#define NBUF 3
#define SMEM_RED WBYTES                // float red[4]
#define SMEM_STAGE (WBYTES + 64)
#define SMEM_TOTAL (SMEM_STAGE + NBUF * ROW_WORDS * 4)   // 108,608 B

__device__ static const int TI[NTILES] = {0,0,0,0,0,0,0,0, 1,1,1,1,1,1, 2,2,2,2, 3,3};
__device__ static const int TJ[NTILES] = {0,1,2,3,4,5,6,7, 2,3,4,5,6,7, 4,5,6,7, 6,7};

__device__ __forceinline__ uint32_t cvt_tf32(uint32_t fbits) {
    uint32_t r;
    asm("cvt.rna.tf32.f32 %0, %1;" : "=r"(r) : "f"(__uint_as_float(fbits)));
    return r;
}

__device__ __forceinline__ void mma_tf32(float* d,
                                         uint32_t a0, uint32_t a1, uint32_t a2, uint32_t a3,
                                         uint32_t b0, uint32_t b1) {
    asm volatile("mma.sync.aligned.m16n8k8.row.col.f32.tf32.tf32.f32 "
                 "{%0,%1,%2,%3}, {%4,%5,%6,%7}, {%8,%9}, {%0,%1,%2,%3};"
                 : "+f"(d[0]), "+f"(d[1]), "+f"(d[2]), "+f"(d[3])
                 : "r"(a0), "r"(a1), "r"(a2), "r"(a3), "r"(b0), "r"(b1));
}

__device__ __forceinline__ uint32_t smem_u32(const void* p) {
    uint32_t a;
    asm("{ .reg .u64 t; cvta.to.shared.u64 t, %1; cvt.u32.u64 %0, t; }"
        : "=r"(a) : "l"(p));
    return a;
}

// Stream one full batch row (32KB) sequentially: 16 x 16B cp.async per
// thread, addresses ascending across the CTA. Destination swizzled:
// word = row*128 + (col ^ ((row&7)<<2)).
__device__ __forceinline__ void issue_row(const float* __restrict__ x,
                                          int b, int B, uint32_t dst_base,
                                          int tid) {
    if (b < B) {
        const int row0 = tid >> 5;             // 0..3
        const int colw = (tid & 31) * 4;       // word col 0..124
        const float* src = x + (size_t)b * ROW_WORDS + row0 * ND + colw;
#pragma unroll
        for (int q = 0; q < 16; ++q) {
            const int row = q * 4 + row0;
            const uint32_t w =
                (uint32_t)(row * ND + (colw ^ ((row & 7) << 2)));
            asm volatile("cp.async.cg.shared.global [%0], [%1], 16;"
                         :: "r"(dst_base + w * 4),
                            "l"(src + (size_t)(q * 4) * ND) : "memory");
        }
    }
    asm volatile("cp.async.commit_group;" ::: "memory");
}

extern "C" __global__ void __launch_bounds__(THREADS, 2)
wfi_mma(const float* __restrict__ x, const float* __restrict__ fw,
        float* __restrict__ out, int B) {
    extern __shared__ char smem[];
    const int tid = threadIdx.x, wq = tid >> 5, lane = tid & 31;
    float* wsm = (float*)smem;
    float* red = (float*)(smem + SMEM_RED);

    // Masked W fragments in mma C-fragment layout.
    for (int idx = tid; idx < NTILES * 128; idx += THREADS) {
        int t = idx >> 7, rem = idx & 127, lp = rem >> 2, r = rem & 3;
        int i = TI[t] * 16 + (lp >> 2) + (r >> 1) * 8;
        int j = TJ[t] * 8 + (lp & 3) * 2 + (r & 1);
        wsm[idx] = (j > i) ? fw[i * NF + j] : 0.0f;
    }
    __syncthreads();

    uint32_t bufa[NBUF];
    const uint32_t* bufw[NBUF];
#pragma unroll
    for (int r = 0; r < NBUF; ++r) {
        int off = SMEM_STAGE + r * ROW_WORDS * 4;
        bufa[r] = smem_u32(smem) + (uint32_t)off;
        bufw[r] = (const uint32_t*)(smem + off);
    }

    const int g  = lane >> 2;
    const int tg = lane & 3;
    const int gsw = g << 2;
    const int b0 = blockIdx.x, G = gridDim.x;

    // Prologue: rows b0, b0+G in flight (bufs 0, 1).
    issue_row(x, b0, B, bufa[0], tid);
    issue_row(x, b0 + G, B, bufa[1], tid);

    int m = 0;
    for (int b = b0; b < B; b += G, ++m) {
        // Buffer (m+2)%3 == (m-1)%3 was released by last iter's barrier.
        issue_row(x, b0 + (m + 2) * G, B, bufa[(m + 2) % NBUF], tid);
        asm volatile("cp.async.wait_group 2;" ::: "memory");
        __syncthreads();                        // row m visible to all warps

        const uint32_t* buf = bufw[m % NBUF];
        float acc[NTILES][4];
#pragma unroll
        for (int t = 0; t < NTILES; ++t)
#pragma unroll
            for (int r = 0; r < 4; ++r) acc[t][r] = 0.0f;

        // Warp wq computes ksteps {wq, wq+4, wq+8, wq+12} over all 20 tiles.
#pragma unroll
        for (int u = 0; u < 4; ++u) {
            const int s = wq + 4 * u;
            uint32_t fx[8], fy[8];
#pragma unroll
            for (int r = 0; r < 8; ++r) {
                const uint32_t base = (8 * r + g) * ND;
                fx[r] = cvt_tf32(buf[base + ((8 * s + tg)     ^ gsw)]);
                fy[r] = cvt_tf32(buf[base + ((8 * s + tg + 4) ^ gsw)]);
            }
#pragma unroll
            for (int t = 0; t < NTILES; ++t) {
                const int ti = TI[t], tj = TJ[t];
                mma_tf32(acc[t], fx[2 * ti], fx[2 * ti + 1],
                         fy[2 * ti], fy[2 * ti + 1], fx[tj], fy[tj]);
            }
        }

        // Weighted reduce of this warp's partial Gram.
        float s = 0.0f;
#pragma unroll
        for (int t = 0; t < NTILES; ++t) {
            float4 w4 = *(const float4*)(wsm + (t * 32 + lane) * 4);
            s = fmaf(w4.x, acc[t][0], s);
            s = fmaf(w4.y, acc[t][1], s);
            s = fmaf(w4.z, acc[t][2], s);
            s = fmaf(w4.w, acc[t][3], s);
        }
#pragma unroll
        for (int off = 16; off > 0; off >>= 1)
            s += __shfl_xor_sync(0xFFFFFFFFu, s, off);
        if (lane == 0) red[wq] = s;

        __syncthreads();                        // compute done; buffer free
        if (tid == 0) out[b] = red[0] + red[1] + red[2] + red[3];
    }
}

extern "C" void kernel_launch(void* const* d_in, const int* in_sizes, int n_in,
                              void* d_out, int out_size) {
    const float* x  = (const float*)d_in[0];
    const float* fw = (const float*)d_in[1];
    float* out      = (float*)d_out;

    int B = in_sizes[0] / (NF * ND);

    int dev = 0, nsm = 148;
    cudaGetDevice(&dev);
    cudaDeviceGetAttribute(&nsm, cudaDevAttrMultiProcessorCount, dev);

    cudaFuncSetAttribute(wfi_mma, cudaFuncAttributeMaxDynamicSharedMemorySize, SMEM_TOTAL);

    int grid = 2 * nsm;                 // 2 CTAs per SM
    wfi_mma<<<grid, THREADS, SMEM_TOTAL>>>(x, fw, out, B);
}